// round 12
// baseline (speedup 1.0000x reference)
#include <cuda_runtime.h>
#include <cuda_fp16.h>
#include <mma.h>
#include <math.h>
#include <cstdint>

using namespace nvcuda;

// ---------------- problem constants ----------------
#define Bb   8
#define Ss   920
#define Dd   1536
#define Hh   4
#define HDd  384
#define Ll   1839
#define BH   32
#define MQ   29440
#define HALFL 919
#define RST  2048                 // padded R row stride (halfs)
#define SROW 1024                 // padded scores row stride (fp32)
#define SZSTR (1024*1024)         // padded scores per-bh slab
#define WN3  (Dd*Hh*HDd)

// ---------------- GEMM tiling (R9 config: best known) ----------------
#define BM 128
#define BNV 128
#define TK 64                     // k-depth per stage (halfs)
#define NSTAGE 3
#define NTHREADS 256
#define LDA 72                    // TK + 8 skew (halfs)

// R/scores fused-launch grid bookkeeping
#define R_GX 15
#define R_GY 230
#define NR_CTAS (R_GX * R_GY)     // 3450
#define NS_CTAS (8 * 8 * BH)      // 2048

// ---------------- scratch ----------------
__device__ __half g_q[BH * Ss * HDd];
__device__ __half g_k[BH * Ss * HDd];
__device__ __half g_vt[BH * HDd * Ss];            // V^T: [bh][d][s]
__device__ __half g_r[(long long)MQ * RST];       // rel bias, HALF, padded
__device__ float  g_s[(long long)BH * SZSTR];     // scores fp32, padded slabs
__device__ __half g_p[(long long)BH * Ss * Ss];   // probs half, packed
__device__ __half g_hs[Bb * Ss * Dd];
__device__ __half g_wt[3 * WN3];                  // W^T half
__device__ __half g_de[Ll * HDd];

// ---------------- helpers ----------------
__device__ __forceinline__ uint32_t smem_u32(const void* p) {
    uint32_t a;
    asm("{ .reg .u64 t; cvta.to.shared.u64 t, %1; cvt.u32.u64 %0, t; }" : "=r"(a) : "l"(p));
    return a;
}
__device__ __forceinline__ void cp16s(uint32_t dst, const void* src, bool p) {
    int sz = p ? 16 : 0;
    asm volatile("cp.async.cg.shared.global [%0], [%1], 16, %2;\n" :: "r"(dst), "l"(src), "r"(sz));
}
__device__ __forceinline__ void cp_commit() { asm volatile("cp.async.commit_group;\n"); }
__device__ __forceinline__ void cp_wait0()  { asm volatile("cp.async.wait_group 0;\n"); }
__device__ __forceinline__ void cp_wait1()  { asm volatile("cp.async.wait_group 1;\n"); }

// ---------------- prep kernels ----------------
__global__ __launch_bounds__(256)
void f2h_copy2(const float4* __restrict__ s0, uint2* __restrict__ d0, int n0,
               const float4* __restrict__ s1, uint2* __restrict__ d1, int n1)
{
    int i = blockIdx.x * 256 + threadIdx.x;
    int st = gridDim.x * 256;
    for (; i < n0 + n1; i += st) {
        const float4* s = (i < n0) ? s0 : s1;
        uint2* d = (i < n0) ? d0 : d1;
        int idx = (i < n0) ? i : (i - n0);
        float4 v = s[idx];
        __half2 h01 = __floats2half2_rn(v.x, v.y);
        __half2 h23 = __floats2half2_rn(v.z, v.w);
        uint2 o;
        o.x = *reinterpret_cast<uint32_t*>(&h01);
        o.y = *reinterpret_cast<uint32_t*>(&h23);
        d[idx] = o;
    }
}

// fused: all three W (1536x1536) -> W^T half slabs; z selects matrix
__global__ __launch_bounds__(256)
void transpose_h3(const float* __restrict__ w0, const float* __restrict__ w1,
                  const float* __restrict__ w2, __half* __restrict__ dst)
{
    __shared__ float t[32][33];
    const int z = blockIdx.z;
    const float* src = (z == 0) ? w0 : (z == 1) ? w1 : w2;
    __half* d = dst + (long long)z * WN3;
    int tx = threadIdx.x, ty = threadIdx.y;
    int x = blockIdx.x * 32 + tx;
    int y0 = blockIdx.y * 32;
    #pragma unroll
    for (int i = 0; i < 32; i += 8)
        t[ty + i][tx] = src[(long long)(y0 + ty + i) * 1536 + x];
    __syncthreads();
    int x2 = blockIdx.y * 32 + tx;
    int y2 = blockIdx.x * 32;
    #pragma unroll
    for (int i = 0; i < 32; i += 8)
        d[(long long)(y2 + ty + i) * 1536 + x2] = __float2half_rn(t[tx][ty + i]);
}

// =======================================================================
// fp16 WMMA NT GEMM body (R9-proven): C = A * B^T, fp32 accum.
// CTA 128x128, 8 warps (2x4), warp tile 64x32. 3-stage cp.async, TK=64.
// EPI 0: fp32 direct store_matrix_sync, padded strides, no guard
// EPI 1: fused QKV (z: 0->Cv(q),1->C1(k),2->C2(vt)); scale only z==0
// EPI 2: ctx: z=(b,h): fp32 out[(b*S+gm)*1536 + h*384 + gn], guarded
// EPI 3: half output, padded row stride ldC, no guard (R)
// BAND: early-exit for R band
// =======================================================================
template<int EPI, bool BAND>
__device__ __forceinline__
void gemm_body(int bx, int by, int bz,
               const __half* __restrict__ A, const __half* __restrict__ B,
               void* __restrict__ Cv,
               int M, int N, int K,
               long long strA, long long strB, long long strC, int ldC,
               float scale, __half* __restrict__ C1, __half* __restrict__ C2)
{
    constexpr int WNv = 32;
    constexpr int NF  = 2;
    constexpr int A_BYTES = BM * LDA * 2;
    constexpr int B_BYTES = BNV * LDA * 2;
    constexpr int STAGE_BYTES = A_BYTES + B_BYTES;   // 36864
    constexpr int LDC = BNV + 4;

    const int m0 = by * BM;
    const int n0 = bx * BNV;

    if (BAND) {
        int mq0 = m0 % Ss;
        int qlo, qhi;
        if (mq0 + (BM - 1) < Ss) { qlo = mq0; qhi = mq0 + BM - 1; }
        else                     { qlo = 0;   qhi = Ss - 1; }
        int lmin = HALFL - qhi, lmax = (Ll - 1) - qlo;
        if (n0 > lmax || n0 + BNV - 1 < lmin) return;
    }

    extern __shared__ char smem[];
    const uint32_t sb = smem_u32(smem);

    const int tid  = threadIdx.x;
    const int warp = tid >> 5;
    const int wm   = warp >> 2;
    const int wn   = warp & 3;
    const int z    = bz;

    A += (long long)z * strA;
    B += (long long)z * strB;
    if (EPI == 1 && z != 0) scale = 1.0f;

    const int nIter = (K + TK - 1) / TK;

    wmma::fragment<wmma::accumulator, 16, 16, 16, float> acc[4][NF];
    #pragma unroll
    for (int i = 0; i < 4; i++)
        #pragma unroll
        for (int j = 0; j < NF; j++)
            wmma::fill_fragment(acc[i][j], 0.0f);

    auto issue_stage = [&](int s) {
        const uint32_t base = sb + (uint32_t)(s % NSTAGE) * STAGE_BYTES;
        const int k0 = s * TK;
        #pragma unroll
        for (int t = 0; t < 4; t++) {
            int idx = tid + t * NTHREADS;
            int r = idx >> 3, c = idx & 7;
            int gm = m0 + r, gk = k0 + c * 8;
            bool p = (gm < M) && (gk < K);
            const __half* src = A + (long long)(p ? gm : 0) * K + (p ? gk : 0);
            cp16s(base + (uint32_t)(r * (LDA * 2) + c * 16), src, p);
        }
        #pragma unroll
        for (int t = 0; t < 4; t++) {
            int idx = tid + t * NTHREADS;
            int r = idx >> 3, c = idx & 7;
            int gn = n0 + r, gk = k0 + c * 8;
            bool p = (gn < N) && (gk < K);
            const __half* src = B + (long long)(p ? gn : 0) * K + (p ? gk : 0);
            cp16s(base + (uint32_t)A_BYTES + (uint32_t)(r * (LDA * 2) + c * 16), src, p);
        }
        cp_commit();
    };

    issue_stage(0);
    issue_stage(1);

    for (int it = 0; it < nIter; ++it) {
        const __half* cA = (const __half*)(smem + (it % NSTAGE) * STAGE_BYTES);
        const __half* cB = (const __half*)(smem + (it % NSTAGE) * STAGE_BYTES + A_BYTES);

        if (it + 1 < nIter) cp_wait1(); else cp_wait0();
        __syncthreads();
        if (it + 2 < nIter) issue_stage(it + 2);

        #pragma unroll
        for (int kk = 0; kk < TK; kk += 16) {
            wmma::fragment<wmma::matrix_a, 16, 16, 16, __half, wmma::row_major> af[4];
            #pragma unroll
            for (int i = 0; i < 4; i++)
                wmma::load_matrix_sync(af[i], cA + (wm * 64 + i * 16) * LDA + kk, LDA);
            wmma::fragment<wmma::matrix_b, 16, 16, 16, __half, wmma::col_major> bf[NF];
            #pragma unroll
            for (int j = 0; j < NF; j++)
                wmma::load_matrix_sync(bf[j], cB + (wn * WNv + j * 16) * LDA + kk, LDA);
            #pragma unroll
            for (int i = 0; i < 4; i++)
                #pragma unroll
                for (int j = 0; j < NF; j++)
                    wmma::mma_sync(acc[i][j], af[i], bf[j], acc[i][j]);
        }
    }

    if (EPI == 0) {
        float* Cg = (float*)Cv + (long long)z * strC;
        #pragma unroll
        for (int i = 0; i < 4; i++) {
            int gm = m0 + wm * 64 + i * 16;
            #pragma unroll
            for (int j = 0; j < NF; j++) {
                int gn = n0 + wn * WNv + j * 16;
                wmma::store_matrix_sync(Cg + (long long)gm * ldC + gn,
                                        acc[i][j], ldC, wmma::mem_row_major);
            }
        }
        return;
    }

    __syncthreads();
    float* shC = (float*)smem;   // [BM][LDC]
    #pragma unroll
    for (int i = 0; i < 4; i++)
        #pragma unroll
        for (int j = 0; j < NF; j++)
            wmma::store_matrix_sync(&shC[(wm * 64 + i * 16) * LDC + (wn * WNv + j * 16)],
                                    acc[i][j], LDC, wmma::mem_row_major);
    __syncthreads();

    if (EPI == 3) {
        __half* Cg = (__half*)Cv;
        #pragma unroll 4
        for (int idx = tid; idx < BM * BNV; idx += NTHREADS) {
            int i = idx >> 7, j = idx & 127;
            Cg[(long long)(m0 + i) * ldC + (n0 + j)] = __float2half_rn(shC[i * LDC + j]);
        }
    } else if (EPI == 1 && z == 2) {
        #pragma unroll 4
        for (int idx = tid; idx < BM * BNV; idx += NTHREADS) {
            int i = idx & (BM - 1), j = idx >> 7;
            int gm = m0 + i, gn = n0 + j;
            if (gm >= M || gn >= N) continue;
            float v = shC[i * LDC + j];
            int b2 = gm / Ss, sP = gm - b2 * Ss;
            int h = gn / HDd, d = gn - h * HDd;
            C2[(((long long)(b2 * Hh + h)) * HDd + d) * Ss + sP] = __float2half_rn(v);
        }
    } else {
        #pragma unroll 4
        for (int idx = tid; idx < BM * BNV; idx += NTHREADS) {
            int i = idx >> 7, j = idx & 127;
            int gm = m0 + i, gn = n0 + j;
            if (gm >= M || gn >= N) continue;
            float v = shC[i * LDC + j] * scale;
            if (EPI == 1) {
                int b2 = gm / Ss, sP = gm - b2 * Ss;
                int h = gn / HDd, d = gn - h * HDd;
                __half hv = __float2half_rn(v);
                long long o = (((long long)(b2 * Hh + h)) * Ss + sP) * HDd + d;
                if (z == 0) ((__half*)Cv)[o] = hv; else C1[o] = hv;
            } else { // EPI == 2
                int b2 = z >> 2, h = z & 3;
                ((float*)Cv)[((long long)b2 * Ss + gm) * (Hh * HDd) + h * HDd + gn] = v;
            }
        }
    }
}

// standalone GEMM kernels (zoff shifts blockIdx.z -> z)
template<int EPI, bool BAND>
__global__ __launch_bounds__(NTHREADS, 2)
void gemm_k(const __half* __restrict__ A, const __half* __restrict__ B,
            void* __restrict__ Cv,
            int M, int N, int K,
            long long strA, long long strB, long long strC, int ldC,
            float scale, __half* __restrict__ C1, __half* __restrict__ C2,
            int zoff)
{
    gemm_body<EPI, BAND>(blockIdx.x, blockIdx.y, blockIdx.z + zoff,
                         A, B, Cv, M, N, K, strA, strB, strC, ldC, scale, C1, C2);
}

// fused R (banded, EPI3) + scores (EPI0) in one launch: flattened grid
__global__ __launch_bounds__(NTHREADS, 2)
void gemm_rs(const __half* __restrict__ q, const __half* __restrict__ de,
             __half* __restrict__ r,
             const __half* __restrict__ k, float* __restrict__ s)
{
    int i = blockIdx.x;
    if (i < NR_CTAS) {
        gemm_body<3, true>(i % R_GX, i / R_GX, 0,
                           q, de, (void*)r, MQ, Ll, HDd,
                           0, 0, 0, RST, 1.0f, nullptr, nullptr);
    } else {
        int j = i - NR_CTAS;                  // 0 .. 2047
        gemm_body<0, false>(j & 7, (j >> 3) & 7, j >> 6,
                            q, k, (void*)s, Ss, Ss, HDd,
                            (long long)Ss * HDd, (long long)Ss * HDd,
                            (long long)SZSTR, SROW, 1.0f, nullptr, nullptr);
    }
}

// =======================================================================
// bias + softmax: scores[bh,q,k] += R_half[m, k-q+919]; softmax; half probs
// =======================================================================
__global__ __launch_bounds__(256)
void bias_softmax(const float* __restrict__ sc, const __half* __restrict__ R,
                  __half* __restrict__ P)
{
    const int r = blockIdx.x;
    const int bh = r / Ss, q = r - bh * Ss;
    const float* row = sc + (long long)bh * SZSTR + (long long)q * SROW;
    const __half* rrow = R + (long long)r * RST + (HALFL - q);
    __half* prow = P + (long long)r * Ss;

    const int tid = threadIdx.x, lane = tid & 31, wid = tid >> 5;
    __shared__ float wred[8];

    float vals[4];
    float mx = -1e30f;
    #pragma unroll
    for (int i = 0; i < 4; i++) {
        int k = tid + i * 256;
        float v = -1e30f;
        if (k < Ss) v = row[k] + __half2float(rrow[k]);
        vals[i] = v;
        mx = fmaxf(mx, v);
    }
    #pragma unroll
    for (int o = 16; o > 0; o >>= 1) mx = fmaxf(mx, __shfl_xor_sync(0xffffffffu, mx, o));
    if (lane == 0) wred[wid] = mx;
    __syncthreads();
    mx = wred[0];
    #pragma unroll
    for (int w = 1; w < 8; w++) mx = fmaxf(mx, wred[w]);
    __syncthreads();

    float sum = 0.0f;
    #pragma unroll
    for (int i = 0; i < 4; i++) {
        int k = tid + i * 256;
        float e = 0.0f;
        if (k < Ss) e = __expf(vals[i] - mx);
        vals[i] = e;
        sum += e;
    }
    #pragma unroll
    for (int o = 16; o > 0; o >>= 1) sum += __shfl_xor_sync(0xffffffffu, sum, o);
    if (lane == 0) wred[wid] = sum;
    __syncthreads();
    sum = 0.0f;
    #pragma unroll
    for (int w = 0; w < 8; w++) sum += wred[w];

    const float inv = 1.0f / sum;
    #pragma unroll
    for (int i = 0; i < 4; i++) {
        int k = tid + i * 256;
        if (k < Ss) prow[k] = __float2half_rn(vals[i] * inv);
    }
}

// =======================================================================
extern "C" void kernel_launch(void* const* d_in, const int* in_sizes, int n_in,
                              void* d_out, int out_size)
{
    (void)in_sizes; (void)n_in; (void)out_size;
    const float* hs = (const float*)d_in[0];
    const float* wq = (const float*)d_in[1];
    const float* wk = (const float*)d_in[2];
    const float* wv = (const float*)d_in[3];
    const float* de = (const float*)d_in[4];
    float* out = (float*)d_out;

    __half *q, *k, *vt, *p, *hsr, *wt, *der, *r;
    float *s;
    cudaGetSymbolAddress((void**)&q,   g_q);
    cudaGetSymbolAddress((void**)&k,   g_k);
    cudaGetSymbolAddress((void**)&vt,  g_vt);
    cudaGetSymbolAddress((void**)&r,   g_r);
    cudaGetSymbolAddress((void**)&s,   g_s);
    cudaGetSymbolAddress((void**)&p,   g_p);
    cudaGetSymbolAddress((void**)&hsr, g_hs);
    cudaGetSymbolAddress((void**)&wt,  g_wt);
    cudaGetSymbolAddress((void**)&der, g_de);

    const int stage3 = NSTAGE * ((BM + BNV) * LDA * 2);             // 110592
    const int shC    = BM * (BNV + 4) * 4;                          // 67584
    const int smemST = (stage3 > shC) ? stage3 : shC;               // 110592
    cudaFuncSetAttribute((const void*)gemm_k<1, false>, cudaFuncAttributeMaxDynamicSharedMemorySize, smemST);
    cudaFuncSetAttribute((const void*)gemm_rs,          cudaFuncAttributeMaxDynamicSharedMemorySize, smemST);
    cudaFuncSetAttribute((const void*)gemm_k<2, false>, cudaFuncAttributeMaxDynamicSharedMemorySize, smemST);

    // capture-safe fork resources (fresh per call; few calls total, no device mem)
    cudaStream_t sv;
    cudaStreamCreateWithFlags(&sv, cudaStreamNonBlocking);
    cudaEvent_t ev1, ev2;
    cudaEventCreateWithFlags(&ev1, cudaEventDisableTiming);
    cudaEventCreateWithFlags(&ev2, cudaEventDisableTiming);

    const float inv = 1.0f / sqrtf((float)HDd);
    dim3 blk(NTHREADS);

    // 0) prep: fused f2h (hs + de), fused weight transpose
    f2h_copy2<<<512, 256>>>((const float4*)hs, (uint2*)hsr, (Bb * Ss * Dd) / 4,
                            (const float4*)de, (uint2*)der, (Ll * HDd) / 4);
    transpose_h3<<<dim3(48, 48, 3), dim3(32, 8)>>>(wq, wk, wv, wt);

    // 1a) QK projections (z = 0,1) on main stream
    dim3 gQK(Dd / BNV, (Bb * Ss + BM - 1) / BM, 2);                 // (12, 58, 2)
    gemm_k<1, false><<<gQK, blk, smemST>>>(hsr, wt, q, Bb * Ss, Hh * HDd, Dd,
                                           0, (long long)WN3, 0, 0, inv, k, vt, 0);

    // 1b) V projection forked onto side stream (only ctx consumes vt)
    cudaEventRecord(ev1, 0);
    cudaStreamWaitEvent(sv, ev1, 0);
    dim3 gV(Dd / BNV, (Bb * Ss + BM - 1) / BM, 1);                  // (12, 58, 1)
    gemm_k<1, false><<<gV, blk, smemST, sv>>>(hsr, wt, q, Bb * Ss, Hh * HDd, Dd,
                                              0, (long long)WN3, 0, 0, inv, k, vt, 2);

    // 2+3) R (banded) + scores fused, main stream (needs only q,k)
    gemm_rs<<<NR_CTAS + NS_CTAS, blk, smemST>>>(q, der, r, k, s);

    // 4) bias + softmax (memory-bound; V overlaps its compute-idle window)
    bias_softmax<<<MQ, 256>>>(s, r, p);

    // join: ctx needs vt
    cudaEventRecord(ev2, sv);
    cudaStreamWaitEvent(0, ev2, 0);

    // 5) ctx = P @ Vt^T per bh -> fp32 (B,S,H*HD)
    dim3 gO(HDd / BNV, (Ss + BM - 1) / BM, BH);                     // (3, 8, 32)
    gemm_k<2, false><<<gO, blk, smemST>>>(p, vt, out, Ss, HDd, Ss,
                                          (long long)Ss * Ss, (long long)HDd * Ss,
                                          0, 0, 1.0f, nullptr, nullptr, 0);
}

// round 13
// speedup vs baseline: 1.0313x; 1.0313x over previous
#include <cuda_runtime.h>
#include <cuda_fp16.h>
#include <mma.h>
#include <math.h>
#include <cstdint>

using namespace nvcuda;

// ---------------- problem constants ----------------
#define Bb   8
#define Ss   920
#define Dd   1536
#define Hh   4
#define HDd  384
#define Ll   1839
#define BH   32
#define MQ   29440
#define HALFL 919
#define RST  2048                 // padded R row stride (halfs)
#define SROW 1024                 // padded scores row stride (fp32)
#define SZSTR (1024*1024)         // padded scores per-bh slab
#define WN3  (Dd*Hh*HDd)

// ---------------- GEMM tiling (R9 config: best known) ----------------
#define BM 128
#define BNV 128
#define TK 64                     // k-depth per stage (halfs)
#define NSTAGE 3
#define NTHREADS 256
#define LDA 72                    // TK + 8 skew (halfs)

// mega-launch grid bookkeeping
#define QKV_GX  12
#define QKV_GY  58
#define QK_CTAS (QKV_GX*QKV_GY*2)     // 1392
#define QKV_CTAS (QKV_GX*QKV_GY*3)    // 2088
#define R_GX 15
#define R_GY 230
#define NR_CTAS (R_GX * R_GY)         // 3450
#define NS_CTAS (8 * 8 * BH)          // 2048
#define MEGA_CTAS (QKV_CTAS + NR_CTAS + NS_CTAS)  // 7586

// prep fused grid
#define PREP_F2H_BLKS 512
#define PREP_T_BLKS   (48*48*3)       // 6912
#define PREP_BLKS     (PREP_F2H_BLKS + PREP_T_BLKS)

// ---------------- scratch ----------------
__device__ __half g_q[BH * Ss * HDd];
__device__ __half g_k[BH * Ss * HDd];
__device__ __half g_vt[BH * HDd * Ss];            // V^T: [bh][d][s]
__device__ __half g_r[(long long)MQ * RST];       // rel bias, HALF, padded
__device__ float  g_s[(long long)BH * SZSTR];     // scores fp32, padded slabs
__device__ __half g_p[(long long)BH * Ss * Ss];   // probs half, packed
__device__ __half g_hs[Bb * Ss * Dd];
__device__ __half g_wt[3 * WN3];                  // W^T half
__device__ __half g_de[Ll * HDd];
__device__ unsigned g_ctr;                        // QK completion counter

// ---------------- helpers ----------------
__device__ __forceinline__ uint32_t smem_u32(const void* p) {
    uint32_t a;
    asm("{ .reg .u64 t; cvta.to.shared.u64 t, %1; cvt.u32.u64 %0, t; }" : "=r"(a) : "l"(p));
    return a;
}
__device__ __forceinline__ void cp16s(uint32_t dst, const void* src, bool p) {
    int sz = p ? 16 : 0;
    asm volatile("cp.async.cg.shared.global [%0], [%1], 16, %2;\n" :: "r"(dst), "l"(src), "r"(sz));
}
__device__ __forceinline__ void cp_commit() { asm volatile("cp.async.commit_group;\n"); }
__device__ __forceinline__ void cp_wait0()  { asm volatile("cp.async.wait_group 0;\n"); }
__device__ __forceinline__ void cp_wait1()  { asm volatile("cp.async.wait_group 1;\n"); }

// gate: wait until g_ctr >= need (acquire), then CTA-wide visible
__device__ __forceinline__ void gate_on(unsigned need) {
    if (threadIdx.x == 0) {
        unsigned v;
        while (true) {
            asm volatile("ld.global.acquire.gpu.u32 %0, [%1];" : "=r"(v) : "l"(&g_ctr));
            if (v >= need) break;
            __nanosleep(128);
        }
    }
    __syncthreads();
}

// ---------------- fused prep: f2h(hs,de) + W^T x3 + counter reset ----------
__global__ __launch_bounds__(256)
void prep_fused(const float* __restrict__ hs, const float* __restrict__ de,
                const float* __restrict__ w0, const float* __restrict__ w1,
                const float* __restrict__ w2,
                __half* __restrict__ hsr, __half* __restrict__ der,
                __half* __restrict__ wt)
{
    __shared__ float t[32][33];
    const int b = blockIdx.x;
    const int tid = threadIdx.x;
    if (b == 0 && tid == 0) g_ctr = 0u;

    if (b < PREP_F2H_BLKS) {
        const int n0 = (Bb * Ss * Dd) / 4;
        const int n1 = (Ll * HDd) / 4;
        int i = b * 256 + tid;
        const int st = PREP_F2H_BLKS * 256;
        for (; i < n0 + n1; i += st) {
            const float4* sp = (i < n0) ? (const float4*)hs : (const float4*)de;
            uint2* dp = (i < n0) ? (uint2*)hsr : (uint2*)der;
            int idx = (i < n0) ? i : (i - n0);
            float4 v = sp[idx];
            __half2 h01 = __floats2half2_rn(v.x, v.y);
            __half2 h23 = __floats2half2_rn(v.z, v.w);
            uint2 o;
            o.x = *reinterpret_cast<uint32_t*>(&h01);
            o.y = *reinterpret_cast<uint32_t*>(&h23);
            dp[idx] = o;
        }
    } else {
        int j = b - PREP_F2H_BLKS;            // 0 .. 6911
        int z = j / 2304;
        int rem = j % 2304;
        int bx = rem % 48, by = rem / 48;
        const float* src = (z == 0) ? w0 : (z == 1) ? w1 : w2;
        __half* d = wt + (long long)z * WN3;
        int tx = tid & 31, ty = tid >> 5;     // 32 x 8
        int x = bx * 32 + tx;
        int y0 = by * 32;
        #pragma unroll
        for (int i2 = 0; i2 < 32; i2 += 8)
            t[ty + i2][tx] = src[(long long)(y0 + ty + i2) * 1536 + x];
        __syncthreads();
        int x2 = by * 32 + tx;
        int y2 = bx * 32;
        #pragma unroll
        for (int i2 = 0; i2 < 32; i2 += 8)
            d[(long long)(y2 + ty + i2) * 1536 + x2] = __float2half_rn(t[tx][ty + i2]);
    }
}

// =======================================================================
// fp16 WMMA NT GEMM body (R9-proven): C = A * B^T, fp32 accum.
// CTA 128x128, 8 warps (2x4), warp tile 64x32. 3-stage cp.async, TK=64.
// EPI 0: fp32 direct store_matrix_sync, padded strides, no guard
// EPI 1: fused QKV (z: 0->Cv(q),1->C1(k),2->C2(vt)); scale only z==0
// EPI 2: ctx: z=(b,h): fp32 out[(b*S+gm)*1536 + h*384 + gn], guarded
// EPI 3: half output, padded row stride ldC, no guard (R)
// BAND: early-exit for R band
// =======================================================================
template<int EPI, bool BAND>
__device__ __forceinline__
void gemm_body(int bx, int by, int bz,
               const __half* __restrict__ A, const __half* __restrict__ B,
               void* __restrict__ Cv,
               int M, int N, int K,
               long long strA, long long strB, long long strC, int ldC,
               float scale, __half* __restrict__ C1, __half* __restrict__ C2)
{
    constexpr int WNv = 32;
    constexpr int NF  = 2;
    constexpr int A_BYTES = BM * LDA * 2;
    constexpr int B_BYTES = BNV * LDA * 2;
    constexpr int STAGE_BYTES = A_BYTES + B_BYTES;   // 36864
    constexpr int LDC = BNV + 4;

    const int m0 = by * BM;
    const int n0 = bx * BNV;

    if (BAND) {
        int mq0 = m0 % Ss;
        int qlo, qhi;
        if (mq0 + (BM - 1) < Ss) { qlo = mq0; qhi = mq0 + BM - 1; }
        else                     { qlo = 0;   qhi = Ss - 1; }
        int lmin = HALFL - qhi, lmax = (Ll - 1) - qlo;
        if (n0 > lmax || n0 + BNV - 1 < lmin) return;
    }

    extern __shared__ char smem[];
    const uint32_t sb = smem_u32(smem);

    const int tid  = threadIdx.x;
    const int warp = tid >> 5;
    const int wm   = warp >> 2;
    const int wn   = warp & 3;
    const int z    = bz;

    A += (long long)z * strA;
    B += (long long)z * strB;
    if (EPI == 1 && z != 0) scale = 1.0f;

    const int nIter = (K + TK - 1) / TK;

    wmma::fragment<wmma::accumulator, 16, 16, 16, float> acc[4][NF];
    #pragma unroll
    for (int i = 0; i < 4; i++)
        #pragma unroll
        for (int j = 0; j < NF; j++)
            wmma::fill_fragment(acc[i][j], 0.0f);

    auto issue_stage = [&](int s) {
        const uint32_t base = sb + (uint32_t)(s % NSTAGE) * STAGE_BYTES;
        const int k0 = s * TK;
        #pragma unroll
        for (int t = 0; t < 4; t++) {
            int idx = tid + t * NTHREADS;
            int r = idx >> 3, c = idx & 7;
            int gm = m0 + r, gk = k0 + c * 8;
            bool p = (gm < M) && (gk < K);
            const __half* src = A + (long long)(p ? gm : 0) * K + (p ? gk : 0);
            cp16s(base + (uint32_t)(r * (LDA * 2) + c * 16), src, p);
        }
        #pragma unroll
        for (int t = 0; t < 4; t++) {
            int idx = tid + t * NTHREADS;
            int r = idx >> 3, c = idx & 7;
            int gn = n0 + r, gk = k0 + c * 8;
            bool p = (gn < N) && (gk < K);
            const __half* src = B + (long long)(p ? gn : 0) * K + (p ? gk : 0);
            cp16s(base + (uint32_t)A_BYTES + (uint32_t)(r * (LDA * 2) + c * 16), src, p);
        }
        cp_commit();
    };

    issue_stage(0);
    issue_stage(1);

    for (int it = 0; it < nIter; ++it) {
        const __half* cA = (const __half*)(smem + (it % NSTAGE) * STAGE_BYTES);
        const __half* cB = (const __half*)(smem + (it % NSTAGE) * STAGE_BYTES + A_BYTES);

        if (it + 1 < nIter) cp_wait1(); else cp_wait0();
        __syncthreads();
        if (it + 2 < nIter) issue_stage(it + 2);

        #pragma unroll
        for (int kk = 0; kk < TK; kk += 16) {
            wmma::fragment<wmma::matrix_a, 16, 16, 16, __half, wmma::row_major> af[4];
            #pragma unroll
            for (int i = 0; i < 4; i++)
                wmma::load_matrix_sync(af[i], cA + (wm * 64 + i * 16) * LDA + kk, LDA);
            wmma::fragment<wmma::matrix_b, 16, 16, 16, __half, wmma::col_major> bf[NF];
            #pragma unroll
            for (int j = 0; j < NF; j++)
                wmma::load_matrix_sync(bf[j], cB + (wn * WNv + j * 16) * LDA + kk, LDA);
            #pragma unroll
            for (int i = 0; i < 4; i++)
                #pragma unroll
                for (int j = 0; j < NF; j++)
                    wmma::mma_sync(acc[i][j], af[i], bf[j], acc[i][j]);
        }
    }

    if (EPI == 0) {
        float* Cg = (float*)Cv + (long long)z * strC;
        #pragma unroll
        for (int i = 0; i < 4; i++) {
            int gm = m0 + wm * 64 + i * 16;
            #pragma unroll
            for (int j = 0; j < NF; j++) {
                int gn = n0 + wn * WNv + j * 16;
                wmma::store_matrix_sync(Cg + (long long)gm * ldC + gn,
                                        acc[i][j], ldC, wmma::mem_row_major);
            }
        }
        return;
    }

    __syncthreads();
    float* shC = (float*)smem;   // [BM][LDC]
    #pragma unroll
    for (int i = 0; i < 4; i++)
        #pragma unroll
        for (int j = 0; j < NF; j++)
            wmma::store_matrix_sync(&shC[(wm * 64 + i * 16) * LDC + (wn * WNv + j * 16)],
                                    acc[i][j], LDC, wmma::mem_row_major);
    __syncthreads();

    if (EPI == 3) {
        __half* Cg = (__half*)Cv;
        #pragma unroll 4
        for (int idx = tid; idx < BM * BNV; idx += NTHREADS) {
            int i = idx >> 7, j = idx & 127;
            Cg[(long long)(m0 + i) * ldC + (n0 + j)] = __float2half_rn(shC[i * LDC + j]);
        }
    } else if (EPI == 1 && z == 2) {
        #pragma unroll 4
        for (int idx = tid; idx < BM * BNV; idx += NTHREADS) {
            int i = idx & (BM - 1), j = idx >> 7;
            int gm = m0 + i, gn = n0 + j;
            if (gm >= M || gn >= N) continue;
            float v = shC[i * LDC + j];
            int b2 = gm / Ss, sP = gm - b2 * Ss;
            int h = gn / HDd, d = gn - h * HDd;
            C2[(((long long)(b2 * Hh + h)) * HDd + d) * Ss + sP] = __float2half_rn(v);
        }
    } else {
        #pragma unroll 4
        for (int idx = tid; idx < BM * BNV; idx += NTHREADS) {
            int i = idx >> 7, j = idx & 127;
            int gm = m0 + i, gn = n0 + j;
            if (gm >= M || gn >= N) continue;
            float v = shC[i * LDC + j] * scale;
            if (EPI == 1) {
                int b2 = gm / Ss, sP = gm - b2 * Ss;
                int h = gn / HDd, d = gn - h * HDd;
                __half hv = __float2half_rn(v);
                long long o = (((long long)(b2 * Hh + h)) * Ss + sP) * HDd + d;
                if (z == 0) ((__half*)Cv)[o] = hv; else C1[o] = hv;
            } else { // EPI == 2
                int b2 = z >> 2, h = z & 3;
                ((float*)Cv)[((long long)b2 * Ss + gm) * (Hh * HDd) + h * HDd + gn] = v;
            }
        }
    }
}

// standalone GEMM kernel (ctx)
template<int EPI, bool BAND>
__global__ __launch_bounds__(NTHREADS, 2)
void gemm_k(const __half* __restrict__ A, const __half* __restrict__ B,
            void* __restrict__ Cv,
            int M, int N, int K,
            long long strA, long long strB, long long strC, int ldC,
            float scale, __half* __restrict__ C1, __half* __restrict__ C2)
{
    gemm_body<EPI, BAND>(blockIdx.x, blockIdx.y, blockIdx.z,
                         A, B, Cv, M, N, K, strA, strB, strC, ldC, scale, C1, C2);
}

// =======================================================================
// mega kernel: [QK 1392][V 696][R 3450][scores 2048] with in-kernel gate.
// QK CTAs signal completion; R/scores CTAs gate on ctr >= QK_CTAS.
// =======================================================================
__global__ __launch_bounds__(NTHREADS, 2)
void mega(const __half* __restrict__ hsr, const __half* __restrict__ wt,
          __half* __restrict__ q, __half* __restrict__ k, __half* __restrict__ vt,
          const __half* __restrict__ de, __half* __restrict__ r,
          float* __restrict__ s, float inv)
{
    const int i = blockIdx.x;
    if (i < QKV_CTAS) {
        int z = i / (QKV_GX * QKV_GY);        // 0,1 = QK; 2 = V
        int rem = i % (QKV_GX * QKV_GY);
        gemm_body<1, false>(rem % QKV_GX, rem / QKV_GX, z,
                            hsr, wt, (void*)q, Bb * Ss, Hh * HDd, Dd,
                            0, (long long)WN3, 0, 0, inv, k, vt);
        if (z < 2) {
            __syncthreads();
            if (threadIdx.x == 0) {
                __threadfence();
                atomicAdd(&g_ctr, 1u);
            }
        }
    } else if (i < QKV_CTAS + NR_CTAS) {
        int j = i - QKV_CTAS;
        int bx = j % R_GX, by = j / R_GX;
        // band pre-check before gating (dead tiles exit instantly)
        {
            int m0 = by * BM;
            int mq0 = m0 % Ss;
            int qlo, qhi;
            if (mq0 + (BM - 1) < Ss) { qlo = mq0; qhi = mq0 + BM - 1; }
            else                     { qlo = 0;   qhi = Ss - 1; }
            int lmin = HALFL - qhi, lmax = (Ll - 1) - qlo;
            int n0 = bx * BNV;
            if (n0 > lmax || n0 + BNV - 1 < lmin) return;
        }
        gate_on(QK_CTAS);
        gemm_body<3, true>(bx, by, 0,
                           q, de, (void*)r, MQ, Ll, HDd,
                           0, 0, 0, RST, 1.0f, nullptr, nullptr);
    } else {
        int j = i - (QKV_CTAS + NR_CTAS);     // 0 .. 2047
        gate_on(QK_CTAS);
        gemm_body<0, false>(j & 7, (j >> 3) & 7, j >> 6,
                            q, k, (void*)s, Ss, Ss, HDd,
                            (long long)Ss * HDd, (long long)Ss * HDd,
                            (long long)SZSTR, SROW, 1.0f, nullptr, nullptr);
    }
}

// =======================================================================
// bias + softmax: scores[bh,q,k] += R_half[m, k-q+919]; softmax; half probs
// =======================================================================
__global__ __launch_bounds__(256)
void bias_softmax(const float* __restrict__ sc, const __half* __restrict__ R,
                  __half* __restrict__ P)
{
    const int r = blockIdx.x;
    const int bh = r / Ss, q = r - bh * Ss;
    const float* row = sc + (long long)bh * SZSTR + (long long)q * SROW;
    const __half* rrow = R + (long long)r * RST + (HALFL - q);
    __half* prow = P + (long long)r * Ss;

    const int tid = threadIdx.x, lane = tid & 31, wid = tid >> 5;
    __shared__ float wred[8];

    float vals[4];
    float mx = -1e30f;
    #pragma unroll
    for (int i = 0; i < 4; i++) {
        int k = tid + i * 256;
        float v = -1e30f;
        if (k < Ss) v = row[k] + __half2float(rrow[k]);
        vals[i] = v;
        mx = fmaxf(mx, v);
    }
    #pragma unroll
    for (int o = 16; o > 0; o >>= 1) mx = fmaxf(mx, __shfl_xor_sync(0xffffffffu, mx, o));
    if (lane == 0) wred[wid] = mx;
    __syncthreads();
    mx = wred[0];
    #pragma unroll
    for (int w = 1; w < 8; w++) mx = fmaxf(mx, wred[w]);
    __syncthreads();

    float sum = 0.0f;
    #pragma unroll
    for (int i = 0; i < 4; i++) {
        int k = tid + i * 256;
        float e = 0.0f;
        if (k < Ss) e = __expf(vals[i] - mx);
        vals[i] = e;
        sum += e;
    }
    #pragma unroll
    for (int o = 16; o > 0; o >>= 1) sum += __shfl_xor_sync(0xffffffffu, sum, o);
    if (lane == 0) wred[wid] = sum;
    __syncthreads();
    sum = 0.0f;
    #pragma unroll
    for (int w = 0; w < 8; w++) sum += wred[w];

    const float inv = 1.0f / sum;
    #pragma unroll
    for (int i = 0; i < 4; i++) {
        int k = tid + i * 256;
        if (k < Ss) prow[k] = __float2half_rn(vals[i] * inv);
    }
}

// =======================================================================
extern "C" void kernel_launch(void* const* d_in, const int* in_sizes, int n_in,
                              void* d_out, int out_size)
{
    (void)in_sizes; (void)n_in; (void)out_size;
    const float* hs = (const float*)d_in[0];
    const float* wq = (const float*)d_in[1];
    const float* wk = (const float*)d_in[2];
    const float* wv = (const float*)d_in[3];
    const float* de = (const float*)d_in[4];
    float* out = (float*)d_out;

    __half *q, *k, *vt, *p, *hsr, *wt, *der, *r;
    float *s;
    cudaGetSymbolAddress((void**)&q,   g_q);
    cudaGetSymbolAddress((void**)&k,   g_k);
    cudaGetSymbolAddress((void**)&vt,  g_vt);
    cudaGetSymbolAddress((void**)&r,   g_r);
    cudaGetSymbolAddress((void**)&s,   g_s);
    cudaGetSymbolAddress((void**)&p,   g_p);
    cudaGetSymbolAddress((void**)&hsr, g_hs);
    cudaGetSymbolAddress((void**)&wt,  g_wt);
    cudaGetSymbolAddress((void**)&der, g_de);

    const int stage3 = NSTAGE * ((BM + BNV) * LDA * 2);             // 110592
    const int shC    = BM * (BNV + 4) * 4;                          // 67584
    const int smemST = (stage3 > shC) ? stage3 : shC;               // 110592
    cudaFuncSetAttribute((const void*)mega,             cudaFuncAttributeMaxDynamicSharedMemorySize, smemST);
    cudaFuncSetAttribute((const void*)gemm_k<2, false>, cudaFuncAttributeMaxDynamicSharedMemorySize, smemST);

    const float inv = 1.0f / sqrtf((float)HDd);
    dim3 blk(NTHREADS);

    // 0) fused prep: f2h(hs, de) + 3x W^T + counter reset
    prep_fused<<<PREP_BLKS, 256>>>(hs, de, wq, wk, wv, hsr, der, wt);

    // 1) mega: QK -> (gate) -> V || R || scores, one launch
    mega<<<MEGA_CTAS, blk, smemST>>>(hsr, wt, q, k, vt, der, r, s, inv);

    // 2) bias + softmax -> half probs
    bias_softmax<<<MQ, 256>>>(s, r, p);

    // 3) ctx = P @ Vt^T per bh -> fp32 (B,S,H*HD)
    dim3 gO(HDd / BNV, (Ss + BM - 1) / BM, BH);                     // (3, 8, 32)
    gemm_k<2, false><<<gO, blk, smemST>>>(p, vt, out, Ss, HDd, Ss,
                                          (long long)Ss * Ss, (long long)HDd * Ss,
                                          0, 0, 1.0f, nullptr, nullptr);
}

// round 14
// speedup vs baseline: 1.0417x; 1.0100x over previous
#include <cuda_runtime.h>
#include <cuda_fp16.h>
#include <mma.h>
#include <math.h>
#include <cstdint>

using namespace nvcuda;

// ---------------- problem constants ----------------
#define Bb   8
#define Ss   920
#define Dd   1536
#define Hh   4
#define HDd  384
#define Ll   1839
#define BH   32
#define MQ   29440
#define HALFL 919
#define RST  2048                 // padded R row stride (halfs)
#define SROW 1024                 // padded scores row stride (fp32)
#define SZSTR (1024*1024)         // padded scores per-bh slab
#define WN3  (Dd*Hh*HDd)

// ---------------- GEMM tiling (R9 config: best known) ----------------
#define BM 128
#define BNV 128
#define TK 64
#define NSTAGE 3
#define NTHREADS 256
#define LDA 72

// mega-launch grid bookkeeping
#define QKV_GX  12
#define QKV_GY  58
#define QK_CTAS (QKV_GX*QKV_GY*2)     // 1392
#define V_CTAS  (QKV_GX*QKV_GY)       // 696
#define QKV_CTAS (QKV_GX*QKV_GY*3)    // 2088
#define R_GX 15
#define R_GY 230
#define NR_CTAS (R_GX * R_GY)         // 3450
#define NS_CTAS (8 * 8 * BH)          // 2048
#define NCTX_CTAS (3 * 8 * BH)        // 768
#define MEGA_CTAS (QKV_CTAS + NR_CTAS + NS_CTAS + NCTX_CTAS)  // 8354
#define NUNITS 256                    // softmax units: 32 bh x 8 row-tiles

// prep fused grid
#define PREP_F2H_BLKS 512
#define PREP_T_BLKS   (48*48*3)
#define PREP_BLKS     (PREP_F2H_BLKS + PREP_T_BLKS)

// ---------------- scratch ----------------
__device__ __half g_q[BH * Ss * HDd];
__device__ __half g_k[BH * Ss * HDd];
__device__ __half g_vt[BH * HDd * Ss];
__device__ __half g_r[(long long)MQ * RST];
__device__ float  g_s[(long long)BH * SZSTR];
__device__ __half g_p[(long long)BH * Ss * Ss];
__device__ __half g_hs[Bb * Ss * Dd];
__device__ __half g_wt[3 * WN3];
__device__ __half g_de[Ll * HDd];
__device__ unsigned g_ctr;            // QK completion
__device__ unsigned g_vctr;           // V completion
__device__ unsigned g_rctr;           // R completion (incl. band-dead)
__device__ unsigned g_sm[NUNITS];     // scores CTAs per unit
__device__ unsigned g_done[NUNITS];   // softmax done per unit

// ---------------- helpers ----------------
__device__ __forceinline__ uint32_t smem_u32(const void* p) {
    uint32_t a;
    asm("{ .reg .u64 t; cvta.to.shared.u64 t, %1; cvt.u32.u64 %0, t; }" : "=r"(a) : "l"(p));
    return a;
}
__device__ __forceinline__ void cp16s(uint32_t dst, const void* src, bool p) {
    int sz = p ? 16 : 0;
    asm volatile("cp.async.cg.shared.global [%0], [%1], 16, %2;\n" :: "r"(dst), "l"(src), "r"(sz));
}
__device__ __forceinline__ void cp_commit() { asm volatile("cp.async.commit_group;\n"); }
__device__ __forceinline__ void cp_wait0()  { asm volatile("cp.async.wait_group 0;\n"); }
__device__ __forceinline__ void cp_wait1()  { asm volatile("cp.async.wait_group 1;\n"); }

// spin until *ctr >= need (acquire); CTA-wide
__device__ __forceinline__ void gate_ge(const unsigned* ctr, unsigned need) {
    if (threadIdx.x == 0) {
        unsigned v;
        while (true) {
            asm volatile("ld.global.acquire.gpu.u32 %0, [%1];" : "=r"(v) : "l"(ctr));
            if (v >= need) break;
            __nanosleep(128);
        }
    }
    __syncthreads();
}
// all prior stores of ALL threads visible, then t0 bumps counter
__device__ __forceinline__ void signal_add(unsigned* ctr) {
    __threadfence();
    __syncthreads();
    if (threadIdx.x == 0) atomicAdd(ctr, 1u);
}

// ---------------- fused prep: f2h(hs,de) + W^T x3 + counter reset ----------
__global__ __launch_bounds__(256)
void prep_fused(const float* __restrict__ hs, const float* __restrict__ de,
                const float* __restrict__ w0, const float* __restrict__ w1,
                const float* __restrict__ w2,
                __half* __restrict__ hsr, __half* __restrict__ der,
                __half* __restrict__ wt)
{
    __shared__ float t[32][33];
    const int b = blockIdx.x;
    const int tid = threadIdx.x;
    if (b == 0) {
        if (tid == 0) { g_ctr = 0u; g_vctr = 0u; g_rctr = 0u; }
        if (tid < NUNITS) { g_sm[tid] = 0u; g_done[tid] = 0u; }
    }

    if (b < PREP_F2H_BLKS) {
        const int n0 = (Bb * Ss * Dd) / 4;
        const int n1 = (Ll * HDd) / 4;
        int i = b * 256 + tid;
        const int st = PREP_F2H_BLKS * 256;
        for (; i < n0 + n1; i += st) {
            const float4* sp = (i < n0) ? (const float4*)hs : (const float4*)de;
            uint2* dp = (i < n0) ? (uint2*)hsr : (uint2*)der;
            int idx = (i < n0) ? i : (i - n0);
            float4 v = sp[idx];
            __half2 h01 = __floats2half2_rn(v.x, v.y);
            __half2 h23 = __floats2half2_rn(v.z, v.w);
            uint2 o;
            o.x = *reinterpret_cast<uint32_t*>(&h01);
            o.y = *reinterpret_cast<uint32_t*>(&h23);
            dp[idx] = o;
        }
    } else {
        int j = b - PREP_F2H_BLKS;
        int z = j / 2304;
        int rem = j % 2304;
        int bx = rem % 48, by = rem / 48;
        const float* src = (z == 0) ? w0 : (z == 1) ? w1 : w2;
        __half* d = wt + (long long)z * WN3;
        int tx = tid & 31, ty = tid >> 5;
        int x = bx * 32 + tx;
        int y0 = by * 32;
        #pragma unroll
        for (int i2 = 0; i2 < 32; i2 += 8)
            t[ty + i2][tx] = src[(long long)(y0 + ty + i2) * 1536 + x];
        __syncthreads();
        int x2 = by * 32 + tx;
        int y2 = bx * 32;
        #pragma unroll
        for (int i2 = 0; i2 < 32; i2 += 8)
            d[(long long)(y2 + ty + i2) * 1536 + x2] = __float2half_rn(t[tx][ty + i2]);
    }
}

// =======================================================================
// fp16 WMMA NT GEMM body (R9-proven). EPI as before.
// =======================================================================
template<int EPI, bool BAND>
__device__ __forceinline__
void gemm_body(int bx, int by, int bz,
               const __half* __restrict__ A, const __half* __restrict__ B,
               void* __restrict__ Cv,
               int M, int N, int K,
               long long strA, long long strB, long long strC, int ldC,
               float scale, __half* __restrict__ C1, __half* __restrict__ C2)
{
    constexpr int WNv = 32;
    constexpr int NF  = 2;
    constexpr int A_BYTES = BM * LDA * 2;
    constexpr int B_BYTES = BNV * LDA * 2;
    constexpr int STAGE_BYTES = A_BYTES + B_BYTES;
    constexpr int LDC = BNV + 4;

    const int m0 = by * BM;
    const int n0 = bx * BNV;

    if (BAND) {
        int mq0 = m0 % Ss;
        int qlo, qhi;
        if (mq0 + (BM - 1) < Ss) { qlo = mq0; qhi = mq0 + BM - 1; }
        else                     { qlo = 0;   qhi = Ss - 1; }
        int lmin = HALFL - qhi, lmax = (Ll - 1) - qlo;
        if (n0 > lmax || n0 + BNV - 1 < lmin) return;
    }

    extern __shared__ char smem[];
    const uint32_t sb = smem_u32(smem);

    const int tid  = threadIdx.x;
    const int warp = tid >> 5;
    const int wm   = warp >> 2;
    const int wn   = warp & 3;
    const int z    = bz;

    A += (long long)z * strA;
    B += (long long)z * strB;
    if (EPI == 1 && z != 0) scale = 1.0f;

    const int nIter = (K + TK - 1) / TK;

    wmma::fragment<wmma::accumulator, 16, 16, 16, float> acc[4][NF];
    #pragma unroll
    for (int i = 0; i < 4; i++)
        #pragma unroll
        for (int j = 0; j < NF; j++)
            wmma::fill_fragment(acc[i][j], 0.0f);

    auto issue_stage = [&](int s) {
        const uint32_t base = sb + (uint32_t)(s % NSTAGE) * STAGE_BYTES;
        const int k0 = s * TK;
        #pragma unroll
        for (int t = 0; t < 4; t++) {
            int idx = tid + t * NTHREADS;
            int r = idx >> 3, c = idx & 7;
            int gm = m0 + r, gk = k0 + c * 8;
            bool p = (gm < M) && (gk < K);
            const __half* src = A + (long long)(p ? gm : 0) * K + (p ? gk : 0);
            cp16s(base + (uint32_t)(r * (LDA * 2) + c * 16), src, p);
        }
        #pragma unroll
        for (int t = 0; t < 4; t++) {
            int idx = tid + t * NTHREADS;
            int r = idx >> 3, c = idx & 7;
            int gn = n0 + r, gk = k0 + c * 8;
            bool p = (gn < N) && (gk < K);
            const __half* src = B + (long long)(p ? gn : 0) * K + (p ? gk : 0);
            cp16s(base + (uint32_t)A_BYTES + (uint32_t)(r * (LDA * 2) + c * 16), src, p);
        }
        cp_commit();
    };

    issue_stage(0);
    issue_stage(1);

    for (int it = 0; it < nIter; ++it) {
        const __half* cA = (const __half*)(smem + (it % NSTAGE) * STAGE_BYTES);
        const __half* cB = (const __half*)(smem + (it % NSTAGE) * STAGE_BYTES + A_BYTES);

        if (it + 1 < nIter) cp_wait1(); else cp_wait0();
        __syncthreads();
        if (it + 2 < nIter) issue_stage(it + 2);

        #pragma unroll
        for (int kk = 0; kk < TK; kk += 16) {
            wmma::fragment<wmma::matrix_a, 16, 16, 16, __half, wmma::row_major> af[4];
            #pragma unroll
            for (int i = 0; i < 4; i++)
                wmma::load_matrix_sync(af[i], cA + (wm * 64 + i * 16) * LDA + kk, LDA);
            wmma::fragment<wmma::matrix_b, 16, 16, 16, __half, wmma::col_major> bf[NF];
            #pragma unroll
            for (int j = 0; j < NF; j++)
                wmma::load_matrix_sync(bf[j], cB + (wn * WNv + j * 16) * LDA + kk, LDA);
            #pragma unroll
            for (int i = 0; i < 4; i++)
                #pragma unroll
                for (int j = 0; j < NF; j++)
                    wmma::mma_sync(acc[i][j], af[i], bf[j], acc[i][j]);
        }
    }

    if (EPI == 0) {
        float* Cg = (float*)Cv + (long long)z * strC;
        #pragma unroll
        for (int i = 0; i < 4; i++) {
            int gm = m0 + wm * 64 + i * 16;
            #pragma unroll
            for (int j = 0; j < NF; j++) {
                int gn = n0 + wn * WNv + j * 16;
                wmma::store_matrix_sync(Cg + (long long)gm * ldC + gn,
                                        acc[i][j], ldC, wmma::mem_row_major);
            }
        }
        return;
    }

    __syncthreads();
    float* shC = (float*)smem;
    #pragma unroll
    for (int i = 0; i < 4; i++)
        #pragma unroll
        for (int j = 0; j < NF; j++)
            wmma::store_matrix_sync(&shC[(wm * 64 + i * 16) * LDC + (wn * WNv + j * 16)],
                                    acc[i][j], LDC, wmma::mem_row_major);
    __syncthreads();

    if (EPI == 3) {
        __half* Cg = (__half*)Cv;
        #pragma unroll 4
        for (int idx = tid; idx < BM * BNV; idx += NTHREADS) {
            int i = idx >> 7, j = idx & 127;
            Cg[(long long)(m0 + i) * ldC + (n0 + j)] = __float2half_rn(shC[i * LDC + j]);
        }
    } else if (EPI == 1 && z == 2) {
        #pragma unroll 4
        for (int idx = tid; idx < BM * BNV; idx += NTHREADS) {
            int i = idx & (BM - 1), j = idx >> 7;
            int gm = m0 + i, gn = n0 + j;
            if (gm >= M || gn >= N) continue;
            float v = shC[i * LDC + j];
            int b2 = gm / Ss, sP = gm - b2 * Ss;
            int h = gn / HDd, d = gn - h * HDd;
            C2[(((long long)(b2 * Hh + h)) * HDd + d) * Ss + sP] = __float2half_rn(v);
        }
    } else {
        #pragma unroll 4
        for (int idx = tid; idx < BM * BNV; idx += NTHREADS) {
            int i = idx >> 7, j = idx & 127;
            int gm = m0 + i, gn = n0 + j;
            if (gm >= M || gn >= N) continue;
            float v = shC[i * LDC + j] * scale;
            if (EPI == 1) {
                int b2 = gm / Ss, sP = gm - b2 * Ss;
                int h = gn / HDd, d = gn - h * HDd;
                __half hv = __float2half_rn(v);
                long long o = (((long long)(b2 * Hh + h)) * Ss + sP) * HDd + d;
                if (z == 0) ((__half*)Cv)[o] = hv; else C1[o] = hv;
            } else { // EPI == 2
                int b2 = z >> 2, h = z & 3;
                ((float*)Cv)[((long long)b2 * Ss + gm) * (Hh * HDd) + h * HDd + gn] = v;
            }
        }
    }
}

// =======================================================================
// warp-per-row softmax for one unit (bh, row-tile by): rows by*128..+127
// identical math to the old bias_softmax (fp32 adds, __expf, rn half out)
// =======================================================================
__device__ void unit_softmax(int bh, int by,
                             const float* __restrict__ s,
                             const __half* __restrict__ r,
                             __half* __restrict__ p)
{
    const int warp = threadIdx.x >> 5, lane = threadIdx.x & 31;
    for (int i = warp; i < 128; i += 8) {
        const int q = by * 128 + i;
        if (q >= Ss) return;
        const float* row = s + (long long)bh * SZSTR + (long long)q * SROW;
        const __half* rrow = r + (long long)(bh * Ss + q) * RST + (HALFL - q);
        __half* prow = p + (long long)(bh * Ss + q) * Ss;

        float vals[32];
        float mx = -1e30f;
        #pragma unroll
        for (int j = 0; j < 8; j++) {
            int g = lane + 32 * j;
            if (g < 230) {
                float4 sc = *(const float4*)(row + 4 * g);
                int c = 4 * g;
                vals[4*j+0] = sc.x + __half2float(rrow[c+0]);
                vals[4*j+1] = sc.y + __half2float(rrow[c+1]);
                vals[4*j+2] = sc.z + __half2float(rrow[c+2]);
                vals[4*j+3] = sc.w + __half2float(rrow[c+3]);
            } else {
                vals[4*j+0] = vals[4*j+1] = vals[4*j+2] = vals[4*j+3] = -1e30f;
            }
            mx = fmaxf(mx, fmaxf(fmaxf(vals[4*j], vals[4*j+1]),
                                 fmaxf(vals[4*j+2], vals[4*j+3])));
        }
        #pragma unroll
        for (int o = 16; o > 0; o >>= 1) mx = fmaxf(mx, __shfl_xor_sync(0xffffffffu, mx, o));

        float sum = 0.0f;
        #pragma unroll
        for (int t2 = 0; t2 < 32; t2++) {
            float e = __expf(vals[t2] - mx);
            vals[t2] = e;
            sum += e;
        }
        #pragma unroll
        for (int o = 16; o > 0; o >>= 1) sum += __shfl_xor_sync(0xffffffffu, sum, o);
        const float inv = 1.0f / sum;

        #pragma unroll
        for (int j = 0; j < 8; j++) {
            int g = lane + 32 * j;
            if (g < 230) {
                __half2 h0 = __floats2half2_rn(vals[4*j+0] * inv, vals[4*j+1] * inv);
                __half2 h1 = __floats2half2_rn(vals[4*j+2] * inv, vals[4*j+3] * inv);
                uint2 o2;
                o2.x = *reinterpret_cast<uint32_t*>(&h0);
                o2.y = *reinterpret_cast<uint32_t*>(&h1);
                *reinterpret_cast<uint2*>(prow + 4 * g) = o2;
            }
        }
    }
}

// =======================================================================
// mega: [QK 1392][V 696][R 3450][S 2048 + per-unit softmax][CTX 768]
// =======================================================================
__global__ __launch_bounds__(NTHREADS, 2)
void mega(const __half* __restrict__ hsr, const __half* __restrict__ wt,
          __half* __restrict__ q, __half* __restrict__ k, __half* __restrict__ vt,
          const __half* __restrict__ de, __half* __restrict__ r,
          float* __restrict__ s, __half* __restrict__ p,
          float* __restrict__ out, float inv)
{
    const int i = blockIdx.x;
    if (i < QKV_CTAS) {
        int z = i / V_CTAS;
        int rem = i % V_CTAS;
        gemm_body<1, false>(rem % QKV_GX, rem / QKV_GX, z,
                            hsr, wt, (void*)q, Bb * Ss, Hh * HDd, Dd,
                            0, (long long)WN3, 0, 0, inv, k, vt);
        if (z < 2) signal_add(&g_ctr); else signal_add(&g_vctr);
    } else if (i < QKV_CTAS + NR_CTAS) {
        int j = i - QKV_CTAS;
        int bx = j % R_GX, by = j / R_GX;
        bool dead;
        {
            int m0 = by * BM;
            int mq0 = m0 % Ss;
            int qlo, qhi;
            if (mq0 + (BM - 1) < Ss) { qlo = mq0; qhi = mq0 + BM - 1; }
            else                     { qlo = 0;   qhi = Ss - 1; }
            int lmin = HALFL - qhi, lmax = (Ll - 1) - qlo;
            int n0 = bx * BNV;
            dead = (n0 > lmax || n0 + BNV - 1 < lmin);
        }
        if (!dead) {
            gate_ge(&g_ctr, QK_CTAS);
            gemm_body<3, true>(bx, by, 0,
                               q, de, (void*)r, MQ, Ll, HDd,
                               0, 0, 0, RST, 1.0f, nullptr, nullptr);
        }
        signal_add(&g_rctr);
    } else if (i < QKV_CTAS + NR_CTAS + NS_CTAS) {
        int j = i - (QKV_CTAS + NR_CTAS);     // 0..2047
        gate_ge(&g_ctr, QK_CTAS);
        gemm_body<0, false>(j & 7, (j >> 3) & 7, j >> 6,
                            q, k, (void*)s, Ss, Ss, HDd,
                            (long long)Ss * HDd, (long long)Ss * HDd,
                            (long long)SZSTR, SROW, 1.0f, nullptr, nullptr);
        const int unit = j >> 3;              // bh*8 + by
        __threadfence();
        __syncthreads();
        __shared__ unsigned s_old;
        if (threadIdx.x == 0) s_old = atomicAdd(&g_sm[unit], 1u);
        __syncthreads();
        if (s_old == 7u) {
            gate_ge(&g_rctr, NR_CTAS);
            __threadfence();
            unit_softmax(unit >> 3, unit & 7, s, r, p);
            __threadfence();
            __syncthreads();
            if (threadIdx.x == 0) atomicExch(&g_done[unit], 1u);
        }
    } else {
        int j = i - (QKV_CTAS + NR_CTAS + NS_CTAS);   // 0..767
        int bx = j % 3, by = (j / 3) & 7, bh = j / 24;
        gate_ge(&g_vctr, V_CTAS);
        gate_ge(&g_done[bh * 8 + by], 1u);
        gemm_body<2, false>(bx, by, bh,
                            p, vt, (void*)out, Ss, HDd, Ss,
                            (long long)Ss * Ss, (long long)HDd * Ss,
                            0, 0, 1.0f, nullptr, nullptr);
    }
}

// =======================================================================
extern "C" void kernel_launch(void* const* d_in, const int* in_sizes, int n_in,
                              void* d_out, int out_size)
{
    (void)in_sizes; (void)n_in; (void)out_size;
    const float* hs = (const float*)d_in[0];
    const float* wq = (const float*)d_in[1];
    const float* wk = (const float*)d_in[2];
    const float* wv = (const float*)d_in[3];
    const float* de = (const float*)d_in[4];
    float* out = (float*)d_out;

    __half *q, *k, *vt, *p, *hsr, *wt, *der, *r;
    float *s;
    cudaGetSymbolAddress((void**)&q,   g_q);
    cudaGetSymbolAddress((void**)&k,   g_k);
    cudaGetSymbolAddress((void**)&vt,  g_vt);
    cudaGetSymbolAddress((void**)&r,   g_r);
    cudaGetSymbolAddress((void**)&s,   g_s);
    cudaGetSymbolAddress((void**)&p,   g_p);
    cudaGetSymbolAddress((void**)&hsr, g_hs);
    cudaGetSymbolAddress((void**)&wt,  g_wt);
    cudaGetSymbolAddress((void**)&der, g_de);

    const int stage3 = NSTAGE * ((BM + BNV) * LDA * 2);             // 110592
    const int shC    = BM * (BNV + 4) * 4;                          // 67584
    const int smemST = (stage3 > shC) ? stage3 : shC;               // 110592
    cudaFuncSetAttribute((const void*)mega, cudaFuncAttributeMaxDynamicSharedMemorySize, smemST);

    const float inv = 1.0f / sqrtf((float)HDd);

    // 0) fused prep: f2h(hs, de) + 3x W^T + counter reset
    prep_fused<<<PREP_BLKS, 256>>>(hs, de, wq, wk, wv, hsr, der, wt);

    // 1) mega: the whole attention DAG in one launch
    mega<<<MEGA_CTAS, NTHREADS, smemST>>>(hsr, wt, q, k, vt, der, r, s, p, out, inv);
}

// round 16
// speedup vs baseline: 1.0461x; 1.0042x over previous
#include <cuda_runtime.h>
#include <cuda_fp16.h>
#include <mma.h>
#include <math.h>
#include <cstdint>

using namespace nvcuda;

// ---------------- problem constants ----------------
#define Bb   8
#define Ss   920
#define Dd   1536
#define Hh   4
#define HDd  384
#define Ll   1839
#define BH   32
#define MQ   29440
#define HALFL 919
#define RST  2048                 // padded R row stride (halfs)
#define SROW 1024                 // padded scores row stride (halfs)
#define SZSTR (1024*1024)         // padded scores per-bh slab (elements)
#define WN3  (Dd*Hh*HDd)

// ---------------- GEMM tiling (R9 config: best known) ----------------
#define BM 128
#define BNV 128
#define TK 64
#define NSTAGE 3
#define NTHREADS 256
#define LDA 72

// mega-launch grid bookkeeping
#define QKV_GX  12
#define QKV_GY  58
#define QK_CTAS (QKV_GX*QKV_GY*2)     // 1392
#define V_CTAS  (QKV_GX*QKV_GY)       // 696
#define QKV_CTAS (QKV_GX*QKV_GY*3)    // 2088
#define R_GX 15
#define R_GY 230
#define NR_CTAS (R_GX * R_GY)         // 3450
#define NS_CTAS (8 * 8 * BH)          // 2048
#define NCTX_CTAS (3 * 8 * BH)        // 768
#define MEGA_CTAS (QKV_CTAS + NR_CTAS + NS_CTAS + NCTX_CTAS)  // 8354
#define NUNITS 256                    // softmax units: 32 bh x 8 row-tiles

// prep fused grid
#define PREP_F2H_BLKS 512
#define PREP_T_BLKS   (48*48*3)
#define PREP_BLKS     (PREP_F2H_BLKS + PREP_T_BLKS)

// ---------------- scratch ----------------
__device__ __half g_q[BH * Ss * HDd];
__device__ __half g_k[BH * Ss * HDd];
__device__ __half g_vt[BH * HDd * Ss];
__device__ __half g_r[(long long)MQ * RST];
__device__ __half g_sh[(long long)BH * SZSTR];    // scores HALF, padded slabs
__device__ __half g_p[(long long)BH * Ss * Ss];
__device__ __half g_hs[Bb * Ss * Dd];
__device__ __half g_wt[3 * WN3];
__device__ __half g_de[Ll * HDd];
__device__ unsigned g_ctr;            // QK completion
__device__ unsigned g_vctr;           // V completion
__device__ unsigned g_rdone[R_GY];    // per-row-tile R completion (15 each)
__device__ unsigned g_sm[NUNITS];     // scores CTAs per unit
__device__ unsigned g_done[NUNITS];   // softmax done per unit

// ---------------- helpers ----------------
__device__ __forceinline__ uint32_t smem_u32(const void* p) {
    uint32_t a;
    asm("{ .reg .u64 t; cvta.to.shared.u64 t, %1; cvt.u32.u64 %0, t; }" : "=r"(a) : "l"(p));
    return a;
}
__device__ __forceinline__ void cp16s(uint32_t dst, const void* src, bool p) {
    int sz = p ? 16 : 0;
    asm volatile("cp.async.cg.shared.global [%0], [%1], 16, %2;\n" :: "r"(dst), "l"(src), "r"(sz));
}
__device__ __forceinline__ void cp_commit() { asm volatile("cp.async.commit_group;\n"); }
__device__ __forceinline__ void cp_wait0()  { asm volatile("cp.async.wait_group 0;\n"); }
__device__ __forceinline__ void cp_wait1()  { asm volatile("cp.async.wait_group 1;\n"); }

__device__ __forceinline__ void gate_ge(const unsigned* ctr, unsigned need) {
    if (threadIdx.x == 0) {
        unsigned v;
        while (true) {
            asm volatile("ld.global.acquire.gpu.u32 %0, [%1];" : "=r"(v) : "l"(ctr));
            if (v >= need) break;
            __nanosleep(128);
        }
    }
    __syncthreads();
}
__device__ __forceinline__ void signal_add(unsigned* ctr) {
    __threadfence();
    __syncthreads();
    if (threadIdx.x == 0) atomicAdd(ctr, 1u);
}

// ---------------- fused prep: f2h(hs,de) + W^T x3 + counter reset ----------
__global__ __launch_bounds__(256)
void prep_fused(const float* __restrict__ hs, const float* __restrict__ de,
                const float* __restrict__ w0, const float* __restrict__ w1,
                const float* __restrict__ w2,
                __half* __restrict__ hsr, __half* __restrict__ der,
                __half* __restrict__ wt)
{
    __shared__ float t[32][33];
    const int b = blockIdx.x;
    const int tid = threadIdx.x;
    if (b == 0) {
        if (tid == 0) { g_ctr = 0u; g_vctr = 0u; }
        if (tid < NUNITS) { g_sm[tid] = 0u; g_done[tid] = 0u; }
        if (tid < R_GY) g_rdone[tid] = 0u;
    }

    if (b < PREP_F2H_BLKS) {
        const int n0 = (Bb * Ss * Dd) / 4;
        const int n1 = (Ll * HDd) / 4;
        int i = b * 256 + tid;
        const int st = PREP_F2H_BLKS * 256;
        for (; i < n0 + n1; i += st) {
            const float4* sp = (i < n0) ? (const float4*)hs : (const float4*)de;
            uint2* dp = (i < n0) ? (uint2*)hsr : (uint2*)der;
            int idx = (i < n0) ? i : (i - n0);
            float4 v = sp[idx];
            __half2 h01 = __floats2half2_rn(v.x, v.y);
            __half2 h23 = __floats2half2_rn(v.z, v.w);
            uint2 o;
            o.x = *reinterpret_cast<uint32_t*>(&h01);
            o.y = *reinterpret_cast<uint32_t*>(&h23);
            dp[idx] = o;
        }
    } else {
        int j = b - PREP_F2H_BLKS;
        int z = j / 2304;
        int rem = j % 2304;
        int bx = rem % 48, by = rem / 48;
        const float* src = (z == 0) ? w0 : (z == 1) ? w1 : w2;
        __half* d = wt + (long long)z * WN3;
        int tx = tid & 31, ty = tid >> 5;
        int x = bx * 32 + tx;
        int y0 = by * 32;
        #pragma unroll
        for (int i2 = 0; i2 < 32; i2 += 8)
            t[ty + i2][tx] = src[(long long)(y0 + ty + i2) * 1536 + x];
        __syncthreads();
        int x2 = by * 32 + tx;
        int y2 = bx * 32;
        #pragma unroll
        for (int i2 = 0; i2 < 32; i2 += 8)
            d[(long long)(y2 + ty + i2) * 1536 + x2] = __float2half_rn(t[tx][ty + i2]);
    }
}

// =======================================================================
// fp16 WMMA NT GEMM body (R9-proven).
// EPI 1: fused QKV;  EPI 2: ctx (fp32 out, guarded)
// EPI 3: half output, padded ldC + z*strC slab offset, unguarded (R, scores)
// =======================================================================
template<int EPI, bool BAND>
__device__ __forceinline__
void gemm_body(int bx, int by, int bz,
               const __half* __restrict__ A, const __half* __restrict__ B,
               void* __restrict__ Cv,
               int M, int N, int K,
               long long strA, long long strB, long long strC, int ldC,
               float scale, __half* __restrict__ C1, __half* __restrict__ C2)
{
    constexpr int WNv = 32;
    constexpr int NF  = 2;
    constexpr int A_BYTES = BM * LDA * 2;
    constexpr int B_BYTES = BNV * LDA * 2;
    constexpr int STAGE_BYTES = A_BYTES + B_BYTES;
    constexpr int LDC = BNV + 4;

    const int m0 = by * BM;
    const int n0 = bx * BNV;

    if (BAND) {
        int mq0 = m0 % Ss;
        int qlo, qhi;
        if (mq0 + (BM - 1) < Ss) { qlo = mq0; qhi = mq0 + BM - 1; }
        else                     { qlo = 0;   qhi = Ss - 1; }
        int lmin = HALFL - qhi, lmax = (Ll - 1) - qlo;
        if (n0 > lmax || n0 + BNV - 1 < lmin) return;
    }

    extern __shared__ char smem[];
    const uint32_t sb = smem_u32(smem);

    const int tid  = threadIdx.x;
    const int warp = tid >> 5;
    const int wm   = warp >> 2;
    const int wn   = warp & 3;
    const int z    = bz;

    A += (long long)z * strA;
    B += (long long)z * strB;
    if (EPI == 1 && z != 0) scale = 1.0f;

    const int nIter = (K + TK - 1) / TK;

    wmma::fragment<wmma::accumulator, 16, 16, 16, float> acc[4][NF];
    #pragma unroll
    for (int i = 0; i < 4; i++)
        #pragma unroll
        for (int j = 0; j < NF; j++)
            wmma::fill_fragment(acc[i][j], 0.0f);

    auto issue_stage = [&](int s) {
        const uint32_t base = sb + (uint32_t)(s % NSTAGE) * STAGE_BYTES;
        const int k0 = s * TK;
        #pragma unroll
        for (int t = 0; t < 4; t++) {
            int idx = tid + t * NTHREADS;
            int r = idx >> 3, c = idx & 7;
            int gm = m0 + r, gk = k0 + c * 8;
            bool p = (gm < M) && (gk < K);
            const __half* src = A + (long long)(p ? gm : 0) * K + (p ? gk : 0);
            cp16s(base + (uint32_t)(r * (LDA * 2) + c * 16), src, p);
        }
        #pragma unroll
        for (int t = 0; t < 4; t++) {
            int idx = tid + t * NTHREADS;
            int r = idx >> 3, c = idx & 7;
            int gn = n0 + r, gk = k0 + c * 8;
            bool p = (gn < N) && (gk < K);
            const __half* src = B + (long long)(p ? gn : 0) * K + (p ? gk : 0);
            cp16s(base + (uint32_t)A_BYTES + (uint32_t)(r * (LDA * 2) + c * 16), src, p);
        }
        cp_commit();
    };

    issue_stage(0);
    issue_stage(1);

    for (int it = 0; it < nIter; ++it) {
        const __half* cA = (const __half*)(smem + (it % NSTAGE) * STAGE_BYTES);
        const __half* cB = (const __half*)(smem + (it % NSTAGE) * STAGE_BYTES + A_BYTES);

        if (it + 1 < nIter) cp_wait1(); else cp_wait0();
        __syncthreads();
        if (it + 2 < nIter) issue_stage(it + 2);

        #pragma unroll
        for (int kk = 0; kk < TK; kk += 16) {
            wmma::fragment<wmma::matrix_a, 16, 16, 16, __half, wmma::row_major> af[4];
            #pragma unroll
            for (int i = 0; i < 4; i++)
                wmma::load_matrix_sync(af[i], cA + (wm * 64 + i * 16) * LDA + kk, LDA);
            wmma::fragment<wmma::matrix_b, 16, 16, 16, __half, wmma::col_major> bf[NF];
            #pragma unroll
            for (int j = 0; j < NF; j++)
                wmma::load_matrix_sync(bf[j], cB + (wn * WNv + j * 16) * LDA + kk, LDA);
            #pragma unroll
            for (int i = 0; i < 4; i++)
                #pragma unroll
                for (int j = 0; j < NF; j++)
                    wmma::mma_sync(acc[i][j], af[i], bf[j], acc[i][j]);
        }
    }

    __syncthreads();
    float* shC = (float*)smem;
    #pragma unroll
    for (int i = 0; i < 4; i++)
        #pragma unroll
        for (int j = 0; j < NF; j++)
            wmma::store_matrix_sync(&shC[(wm * 64 + i * 16) * LDC + (wn * WNv + j * 16)],
                                    acc[i][j], LDC, wmma::mem_row_major);
    __syncthreads();

    if (EPI == 3) {
        __half* Cg = (__half*)Cv + (long long)z * strC;
        #pragma unroll 4
        for (int idx = tid; idx < BM * BNV; idx += NTHREADS) {
            int i = idx >> 7, j = idx & 127;
            Cg[(long long)(m0 + i) * ldC + (n0 + j)] = __float2half_rn(shC[i * LDC + j]);
        }
    } else if (EPI == 1 && z == 2) {
        #pragma unroll 4
        for (int idx = tid; idx < BM * BNV; idx += NTHREADS) {
            int i = idx & (BM - 1), j = idx >> 7;
            int gm = m0 + i, gn = n0 + j;
            if (gm >= M || gn >= N) continue;
            float v = shC[i * LDC + j];
            int b2 = gm / Ss, sP = gm - b2 * Ss;
            int h = gn / HDd, d = gn - h * HDd;
            C2[(((long long)(b2 * Hh + h)) * HDd + d) * Ss + sP] = __float2half_rn(v);
        }
    } else {
        #pragma unroll 4
        for (int idx = tid; idx < BM * BNV; idx += NTHREADS) {
            int i = idx >> 7, j = idx & 127;
            int gm = m0 + i, gn = n0 + j;
            if (gm >= M || gn >= N) continue;
            float v = shC[i * LDC + j] * scale;
            if (EPI == 1) {
                int b2 = gm / Ss, sP = gm - b2 * Ss;
                int h = gn / HDd, d = gn - h * HDd;
                __half hv = __float2half_rn(v);
                long long o = (((long long)(b2 * Hh + h)) * Ss + sP) * HDd + d;
                if (z == 0) ((__half*)Cv)[o] = hv; else C1[o] = hv;
            } else { // EPI == 2
                int b2 = z >> 2, h = z & 3;
                ((float*)Cv)[((long long)b2 * Ss + gm) * (Hh * HDd) + h * HDd + gn] = v;
            }
        }
    }
}

// =======================================================================
// warp-per-row softmax for one unit (bh, row-tile by): HALF scores in
// =======================================================================
__device__ void unit_softmax(int bh, int by,
                             const __half* __restrict__ sh,
                             const __half* __restrict__ r,
                             __half* __restrict__ p)
{
    const int warp = threadIdx.x >> 5, lane = threadIdx.x & 31;
    for (int i = warp; i < 128; i += 8) {
        const int q = by * 128 + i;
        if (q >= Ss) return;
        const __half* row = sh + (long long)bh * SZSTR + (long long)q * SROW;
        const __half* rrow = r + (long long)(bh * Ss + q) * RST + (HALFL - q);
        __half* prow = p + (long long)(bh * Ss + q) * Ss;

        float vals[32];
        float mx = -1e30f;
        #pragma unroll
        for (int j = 0; j < 8; j++) {
            int g = lane + 32 * j;
            if (g < 230) {
                uint2 sc = *(const uint2*)(row + 4 * g);
                __half2 s01 = *reinterpret_cast<__half2*>(&sc.x);
                __half2 s23 = *reinterpret_cast<__half2*>(&sc.y);
                int c = 4 * g;
                vals[4*j+0] = __low2float(s01)  + __half2float(rrow[c+0]);
                vals[4*j+1] = __high2float(s01) + __half2float(rrow[c+1]);
                vals[4*j+2] = __low2float(s23)  + __half2float(rrow[c+2]);
                vals[4*j+3] = __high2float(s23) + __half2float(rrow[c+3]);
            } else {
                vals[4*j+0] = vals[4*j+1] = vals[4*j+2] = vals[4*j+3] = -1e30f;
            }
            mx = fmaxf(mx, fmaxf(fmaxf(vals[4*j], vals[4*j+1]),
                                 fmaxf(vals[4*j+2], vals[4*j+3])));
        }
        #pragma unroll
        for (int o = 16; o > 0; o >>= 1) mx = fmaxf(mx, __shfl_xor_sync(0xffffffffu, mx, o));

        float sum = 0.0f;
        #pragma unroll
        for (int t2 = 0; t2 < 32; t2++) {
            float e = __expf(vals[t2] - mx);
            vals[t2] = e;
            sum += e;
        }
        #pragma unroll
        for (int o = 16; o > 0; o >>= 1) sum += __shfl_xor_sync(0xffffffffu, sum, o);
        const float inv = 1.0f / sum;

        #pragma unroll
        for (int j = 0; j < 8; j++) {
            int g = lane + 32 * j;
            if (g < 230) {
                __half2 h0 = __floats2half2_rn(vals[4*j+0] * inv, vals[4*j+1] * inv);
                __half2 h1 = __floats2half2_rn(vals[4*j+2] * inv, vals[4*j+3] * inv);
                uint2 o2;
                o2.x = *reinterpret_cast<uint32_t*>(&h0);
                o2.y = *reinterpret_cast<uint32_t*>(&h1);
                *reinterpret_cast<uint2*>(prow + 4 * g) = o2;
            }
        }
    }
}

// =======================================================================
// mega: [QK 1392][V 696][R 3450][S 2048 + per-unit softmax][CTX 768]
// =======================================================================
__global__ __launch_bounds__(NTHREADS, 2)
void mega(const __half* __restrict__ hsr, const __half* __restrict__ wt,
          __half* __restrict__ q, __half* __restrict__ k, __half* __restrict__ vt,
          const __half* __restrict__ de, __half* __restrict__ r,
          __half* __restrict__ sh, __half* __restrict__ p,
          float* __restrict__ out, float inv)
{
    const int i = blockIdx.x;
    if (i < QKV_CTAS) {
        int z = i / V_CTAS;
        int rem = i % V_CTAS;
        gemm_body<1, false>(rem % QKV_GX, rem / QKV_GX, z,
                            hsr, wt, (void*)q, Bb * Ss, Hh * HDd, Dd,
                            0, (long long)WN3, 0, 0, inv, k, vt);
        if (z < 2) signal_add(&g_ctr); else signal_add(&g_vctr);
    } else if (i < QKV_CTAS + NR_CTAS) {
        int j = i - QKV_CTAS;
        int bx = j % R_GX, by = j / R_GX;
        bool dead;
        {
            int m0 = by * BM;
            int mq0 = m0 % Ss;
            int qlo, qhi;
            if (mq0 + (BM - 1) < Ss) { qlo = mq0; qhi = mq0 + BM - 1; }
            else                     { qlo = 0;   qhi = Ss - 1; }
            int lmin = HALFL - qhi, lmax = (Ll - 1) - qlo;
            int n0 = bx * BNV;
            dead = (n0 > lmax || n0 + BNV - 1 < lmin);
        }
        if (!dead) {
            gate_ge(&g_ctr, QK_CTAS);
            gemm_body<3, true>(bx, by, 0,
                               q, de, (void*)r, MQ, Ll, HDd,
                               0, 0, 0, RST, 1.0f, nullptr, nullptr);
        }
        signal_add(&g_rdone[by]);
    } else if (i < QKV_CTAS + NR_CTAS + NS_CTAS) {
        int j = i - (QKV_CTAS + NR_CTAS);     // 0..2047
        gate_ge(&g_ctr, QK_CTAS);
        gemm_body<3, false>(j & 7, (j >> 3) & 7, j >> 6,
                            q, k, (void*)sh, Ss, Ss, HDd,
                            (long long)Ss * HDd, (long long)Ss * HDd,
                            (long long)SZSTR, SROW, 1.0f, nullptr, nullptr);
        const int unit = j >> 3;              // bh*8 + by
        __threadfence();
        __syncthreads();
        __shared__ unsigned s_old;
        if (threadIdx.x == 0) s_old = atomicAdd(&g_sm[unit], 1u);
        __syncthreads();
        if (s_old == 7u) {
            const int bh = unit >> 3, by = unit & 7;
            // R rows actually used: m in [bh*920 + by*128, bh*920 + min(by*128+127, 919)]
            int qhiu = by * 128 + 127;
            if (qhiu > Ss - 1) qhiu = Ss - 1;
            int mlo = bh * Ss + by * 128;
            int mhi = bh * Ss + qhiu;
            int t0 = mlo >> 7, t1 = mhi >> 7;     // both guaranteed <= 229
            gate_ge(&g_rdone[t0], R_GX);
            if (t1 != t0) gate_ge(&g_rdone[t1], R_GX);
            __threadfence();
            unit_softmax(bh, by, sh, r, p);
            __threadfence();
            __syncthreads();
            if (threadIdx.x == 0) atomicExch(&g_done[unit], 1u);
        }
    } else {
        int j = i - (QKV_CTAS + NR_CTAS + NS_CTAS);   // 0..767
        int bx = j % 3, by = (j / 3) & 7, bh = j / 24;
        gate_ge(&g_vctr, V_CTAS);
        gate_ge(&g_done[bh * 8 + by], 1u);
        gemm_body<2, false>(bx, by, bh,
                            p, vt, (void*)out, Ss, HDd, Ss,
                            (long long)Ss * Ss, (long long)HDd * Ss,
                            0, 0, 1.0f, nullptr, nullptr);
    }
}

// =======================================================================
extern "C" void kernel_launch(void* const* d_in, const int* in_sizes, int n_in,
                              void* d_out, int out_size)
{
    (void)in_sizes; (void)n_in; (void)out_size;
    const float* hs = (const float*)d_in[0];
    const float* wq = (const float*)d_in[1];
    const float* wk = (const float*)d_in[2];
    const float* wv = (const float*)d_in[3];
    const float* de = (const float*)d_in[4];
    float* out = (float*)d_out;

    __half *q, *k, *vt, *p, *hsr, *wt, *der, *r, *sh;
    cudaGetSymbolAddress((void**)&q,   g_q);
    cudaGetSymbolAddress((void**)&k,   g_k);
    cudaGetSymbolAddress((void**)&vt,  g_vt);
    cudaGetSymbolAddress((void**)&r,   g_r);
    cudaGetSymbolAddress((void**)&sh,  g_sh);
    cudaGetSymbolAddress((void**)&p,   g_p);
    cudaGetSymbolAddress((void**)&hsr, g_hs);
    cudaGetSymbolAddress((void**)&wt,  g_wt);
    cudaGetSymbolAddress((void**)&der, g_de);

    const int stage3 = NSTAGE * ((BM + BNV) * LDA * 2);             // 110592
    const int shC    = BM * (BNV + 4) * 4;                          // 67584
    const int smemST = (stage3 > shC) ? stage3 : shC;               // 110592
    cudaFuncSetAttribute((const void*)mega, cudaFuncAttributeMaxDynamicSharedMemorySize, smemST);

    const float inv = 1.0f / sqrtf((float)HDd);

    // 0) fused prep: f2h(hs, de) + 3x W^T + counter reset
    prep_fused<<<PREP_BLKS, 256>>>(hs, de, wq, wk, wv, hsr, der, wt);

    // 1) mega: the whole attention DAG in one launch
    mega<<<MEGA_CTAS, NTHREADS, smemST>>>(hsr, wt, q, k, vt, der, r, sh, p, out, inv);
}